// round 1
// baseline (speedup 1.0000x reference)
#include <cuda_runtime.h>

#define NN 8192
#define NE 65536

// ---------------- scratch (device globals; no allocations allowed) ----------
__device__ float g_T1[NN * 48 * 12];   // per node, per o(48): [f0..f7, bias, 0,0,0]
__device__ float g_T2[NN * 32 * 12];   // per node, per o(32): same layout
__device__ float g_agg1[NN * 48];
__device__ float g_h1[NN * 48];
__device__ float g_agg2[NN * 32];
__device__ float g_h2[NN * 32];
__device__ float g_hm[NN * 16];
__device__ float g_hl[NN * 16];
__device__ float g_aggm[NN * 16];
__device__ float g_aggl[NN * 16];
__device__ float g_deg[NN];
__device__ float g_dinv[NN];
__device__ float g_invdeg[NN];
__device__ float g_Wt1[64 * 432];      // [i][c] with c = o*9+s  (s<8: nn1_w, s==8: nn1_b)
__device__ float g_Wt2[48 * 288];

// ---------------- weight transpose: W[f, i*CO+o]/B[i*CO+o] -> Wt[i*NC + (o*9+s)]
template<int K, int CO>
__global__ void wtrans_kernel(const float* __restrict__ W, const float* __restrict__ B,
                              float* __restrict__ Wt) {
    constexpr int NC = CO * 9;
    int idx = blockIdx.x * 256 + threadIdx.x;
    if (idx < K * NC) {
        int i = idx / NC;
        int c = idx - i * NC;
        int o = c / 9, s = c - o * 9;
        Wt[idx] = (s == 8) ? B[i * CO + o] : W[s * (K * CO) + i * CO + o];
    }
}

// ---------------- node GEMM: T[n, o*12+s] = sum_i X[n,i] * Wt[i, o*9+s] -----
// tile: 32 nodes x 128 cols; 256 threads; each thread: 8 nodes x 2 cols.
template<int K, int CO>
__global__ void node_gemm_kernel(const float* __restrict__ X, const float* __restrict__ Wt,
                                 float* __restrict__ T) {
    constexpr int NC = CO * 9;
    __shared__ float xs[32][K];
    int n0 = blockIdx.y * 32;
    for (int idx = threadIdx.x; idx < 32 * K; idx += 256)
        xs[idx / K][idx % K] = X[n0 * K + idx];
    __syncthreads();

    int tx = threadIdx.x & 63;
    int ng = threadIdx.x >> 6;          // node group 0..3 (8 nodes each)
    int c0 = blockIdx.x * 128 + tx;
    int c1 = c0 + 64;
    bool a0 = c0 < NC, a1 = c1 < NC;

    float acc0[8], acc1[8];
#pragma unroll
    for (int j = 0; j < 8; j++) { acc0[j] = 0.f; acc1[j] = 0.f; }

    const float* w0 = Wt + c0;
    const float* w1 = Wt + c1;
#pragma unroll 4
    for (int i = 0; i < K; i++) {
        float wv0 = a0 ? w0[i * NC] : 0.f;
        float wv1 = a1 ? w1[i * NC] : 0.f;
#pragma unroll
        for (int j = 0; j < 8; j++) {
            float xv = xs[ng * 8 + j][i];
            acc0[j] += xv * wv0;
            acc1[j] += xv * wv1;
        }
    }

    int nb = n0 + ng * 8;
    if (a0) {
        int o = c0 / 9, s = c0 - o * 9;
#pragma unroll
        for (int j = 0; j < 8; j++) T[(nb + j) * (CO * 12) + o * 12 + s] = acc0[j];
        if (s == 8) {
#pragma unroll
            for (int j = 0; j < 8; j++) {
                int r = (nb + j) * (CO * 12) + o * 12;
                T[r + 9] = 0.f; T[r + 10] = 0.f; T[r + 11] = 0.f;
            }
        }
    }
    if (a1) {
        int o = c1 / 9, s = c1 - o * 9;
#pragma unroll
        for (int j = 0; j < 8; j++) T[(nb + j) * (CO * 12) + o * 12 + s] = acc1[j];
        if (s == 8) {
#pragma unroll
            for (int j = 0; j < 8; j++) {
                int r = (nb + j) * (CO * 12) + o * 12;
                T[r + 9] = 0.f; T[r + 10] = 0.f; T[r + 11] = 0.f;
            }
        }
    }
}

// ---------------- edge NNConv: msg_e[o] = bias + sum_f ea[e,f]*T[src][o][f]; scatter to dst
template<int CO>
__global__ void edge_nnconv_kernel(const int* __restrict__ ei, const float* __restrict__ ea,
                                   const float* __restrict__ T, float* __restrict__ agg) {
    constexpr int EB = (CO == 48) ? 16 : 32;      // edges per block
    constexpr int ITEMS = EB * CO / 256;          // 3 or 4
    __shared__ int s_src[EB], s_dst[EB];
    __shared__ __align__(16) float s_ea[EB * 8];
    int e0 = blockIdx.x * EB;
    if (threadIdx.x < EB) {
        s_src[threadIdx.x] = ei[e0 + threadIdx.x];
        s_dst[threadIdx.x] = ei[NE + e0 + threadIdx.x];
    }
    for (int idx = threadIdx.x; idx < EB * 8; idx += 256) s_ea[idx] = ea[e0 * 8 + idx];
    __syncthreads();

#pragma unroll
    for (int j = 0; j < ITEMS; j++) {
        int item = threadIdx.x + j * 256;
        int el = item / CO, o = item - el * CO;
        int src = s_src[el], dst = s_dst[el];
        const float4* tp = reinterpret_cast<const float4*>(T + src * (CO * 12) + o * 12);
        float4 t0 = tp[0], t1 = tp[1], t2 = tp[2];
        const float4* ep = reinterpret_cast<const float4*>(s_ea + el * 8);
        float4 a0 = ep[0], a1 = ep[1];
        float m = t2.x
                + a0.x * t0.x + a0.y * t0.y + a0.z * t0.z + a0.w * t0.w
                + a1.x * t1.x + a1.y * t1.y + a1.z * t1.z + a1.w * t1.w;
        atomicAdd(&agg[dst * CO + o], m);
    }
}

// ---------------- H = relu(agg + X @ root + bias) ---------------------------
template<int K, int CO>
__global__ void root_relu_kernel(const float* __restrict__ agg, const float* __restrict__ X,
                                 const float* __restrict__ root, const float* __restrict__ bias,
                                 float* __restrict__ H) {
    constexpr int NB = 16;
    constexpr int ITEMS = NB * CO / 256;
    __shared__ float xs[NB][K];
    int n0 = blockIdx.x * NB;
    for (int idx = threadIdx.x; idx < NB * K; idx += 256)
        xs[idx / K][idx % K] = X[n0 * K + idx];
    __syncthreads();
#pragma unroll
    for (int j = 0; j < ITEMS; j++) {
        int item = threadIdx.x + j * 256;
        int nl = item / CO, o = item - nl * CO;
        float acc = agg[(n0 + nl) * CO + o] + bias[o];
#pragma unroll 4
        for (int i = 0; i < K; i++) acc += xs[nl][i] * root[i * CO + o];
        H[(n0 + nl) * CO + o] = fmaxf(acc, 0.f);
    }
}

// ---------------- GCN head projections: hm = H@mu_w, hl = H@ls_w ------------
__global__ void heads_kernel(const float* __restrict__ H, const float* __restrict__ muw,
                             const float* __restrict__ lsw,
                             float* __restrict__ hm, float* __restrict__ hl) {
    __shared__ float hs[16][32];
    int n0 = blockIdx.x * 16;
    for (int idx = threadIdx.x; idx < 512; idx += 256)
        (&hs[0][0])[idx] = H[n0 * 32 + idx];
    __syncthreads();
#pragma unroll
    for (int j = 0; j < 2; j++) {
        int item = threadIdx.x + j * 256;
        int nl = item >> 5;
        int r = item & 31;
        int head = r >> 4;
        int o = r & 15;
        const float* W = head ? lsw : muw;
        float acc = 0.f;
#pragma unroll
        for (int i = 0; i < 32; i++) acc += hs[nl][i] * W[i * 16 + o];
        float* dst = head ? hl : hm;
        dst[(n0 + nl) * 16 + o] = acc;
    }
}

// ---------------- degree & normalization ------------------------------------
__global__ void deg_kernel(const int* __restrict__ ei, float* __restrict__ deg) {
    int e = blockIdx.x * 256 + threadIdx.x;
    if (e < NE) atomicAdd(&deg[ei[NE + e]], 1.0f);
}
__global__ void dinv_kernel(const float* __restrict__ deg, float* __restrict__ dinv,
                            float* __restrict__ invdeg) {
    int n = blockIdx.x * 256 + threadIdx.x;
    if (n < NN) {
        float d = deg[n] + 1.0f;
        dinv[n] = rsqrtf(d);
        invdeg[n] = 1.0f / d;
    }
}

// ---------------- GCN edge scatter: agg[dst] += h[src]*dinv[src]*dinv[dst] --
__global__ void gcn_edge_kernel(const int* __restrict__ ei, const float* __restrict__ hm,
                                const float* __restrict__ hl, const float* __restrict__ dinv,
                                float* __restrict__ aggm, float* __restrict__ aggl) {
    __shared__ int s_src[16], s_dst[16];
    __shared__ float s_w[16];
    int e0 = blockIdx.x * 16;
    if (threadIdx.x < 16) {
        int s = ei[e0 + threadIdx.x], d = ei[NE + e0 + threadIdx.x];
        s_src[threadIdx.x] = s;
        s_dst[threadIdx.x] = d;
        s_w[threadIdx.x] = dinv[s] * dinv[d];
    }
    __syncthreads();
    int el = threadIdx.x >> 4, o = threadIdx.x & 15;
    int src = s_src[el], dst = s_dst[el];
    float w = s_w[el];
    atomicAdd(&aggm[dst * 16 + o], hm[src * 16 + o] * w);
    atomicAdd(&aggl[dst * 16 + o], hl[src * 16 + o] * w);
}

// ---------------- final: out = agg + h*invdeg + bias (mu then ls) -----------
__global__ void out_kernel(const float* __restrict__ aggm, const float* __restrict__ aggl,
                           const float* __restrict__ hm, const float* __restrict__ hl,
                           const float* __restrict__ invdeg, const float* __restrict__ mub,
                           const float* __restrict__ lsb, float* __restrict__ out) {
    int idx = blockIdx.x * 256 + threadIdx.x;
    if (idx < NN * 16) {
        int n = idx >> 4, o = idx & 15;
        float iv = invdeg[n];
        out[idx]           = aggm[idx] + hm[idx] * iv + mub[o];
        out[NN * 16 + idx] = aggl[idx] + hl[idx] * iv + lsb[o];
    }
}

// ---------------- launcher --------------------------------------------------
extern "C" void kernel_launch(void* const* d_in, const int* in_sizes, int n_in,
                              void* d_out, int out_size) {
    const float* x      = (const float*)d_in[0];
    const int*   ei     = (const int*)  d_in[1];
    const float* ea     = (const float*)d_in[2];
    const float* nn1_w  = (const float*)d_in[3];
    const float* nn1_b  = (const float*)d_in[4];
    const float* root1  = (const float*)d_in[5];
    const float* bias1  = (const float*)d_in[6];
    const float* nn2_w  = (const float*)d_in[7];
    const float* nn2_b  = (const float*)d_in[8];
    const float* root2  = (const float*)d_in[9];
    const float* bias2  = (const float*)d_in[10];
    const float* mu_w   = (const float*)d_in[11];
    const float* mu_b   = (const float*)d_in[12];
    const float* ls_w   = (const float*)d_in[13];
    const float* ls_b   = (const float*)d_in[14];
    float* out = (float*)d_out;

    void *pT1, *pT2, *pagg1, *ph1, *pagg2, *ph2, *phm, *phl, *paggm, *paggl;
    void *pdeg, *pdinv, *pinvdeg, *pWt1, *pWt2;
    cudaGetSymbolAddress(&pT1, g_T1);
    cudaGetSymbolAddress(&pT2, g_T2);
    cudaGetSymbolAddress(&pagg1, g_agg1);
    cudaGetSymbolAddress(&ph1, g_h1);
    cudaGetSymbolAddress(&pagg2, g_agg2);
    cudaGetSymbolAddress(&ph2, g_h2);
    cudaGetSymbolAddress(&phm, g_hm);
    cudaGetSymbolAddress(&phl, g_hl);
    cudaGetSymbolAddress(&paggm, g_aggm);
    cudaGetSymbolAddress(&paggl, g_aggl);
    cudaGetSymbolAddress(&pdeg, g_deg);
    cudaGetSymbolAddress(&pdinv, g_dinv);
    cudaGetSymbolAddress(&pinvdeg, g_invdeg);
    cudaGetSymbolAddress(&pWt1, g_Wt1);
    cudaGetSymbolAddress(&pWt2, g_Wt2);

    cudaMemsetAsync(pagg1, 0, NN * 48 * sizeof(float), 0);
    cudaMemsetAsync(pagg2, 0, NN * 32 * sizeof(float), 0);
    cudaMemsetAsync(paggm, 0, NN * 16 * sizeof(float), 0);
    cudaMemsetAsync(paggl, 0, NN * 16 * sizeof(float), 0);
    cudaMemsetAsync(pdeg,  0, NN * sizeof(float), 0);

    wtrans_kernel<64, 48><<<(64 * 432 + 255) / 256, 256>>>(nn1_w, nn1_b, (float*)pWt1);
    wtrans_kernel<48, 32><<<(48 * 288 + 255) / 256, 256>>>(nn2_w, nn2_b, (float*)pWt2);
    deg_kernel<<<NE / 256, 256>>>(ei, (float*)pdeg);
    dinv_kernel<<<NN / 256, 256>>>((float*)pdeg, (float*)pdinv, (float*)pinvdeg);

    // layer 1
    node_gemm_kernel<64, 48><<<dim3(4, 256), 256>>>(x, (float*)pWt1, (float*)pT1);
    edge_nnconv_kernel<48><<<NE / 16, 256>>>(ei, ea, (float*)pT1, (float*)pagg1);
    root_relu_kernel<64, 48><<<NN / 16, 256>>>((float*)pagg1, x, root1, bias1, (float*)ph1);

    // layer 2
    node_gemm_kernel<48, 32><<<dim3(3, 256), 256>>>((float*)ph1, (float*)pWt2, (float*)pT2);
    edge_nnconv_kernel<32><<<NE / 32, 256>>>(ei, ea, (float*)pT2, (float*)pagg2);
    root_relu_kernel<48, 32><<<NN / 16, 256>>>((float*)pagg2, (float*)ph1, root2, bias2, (float*)ph2);

    // GCN heads
    heads_kernel<<<NN / 16, 256>>>((float*)ph2, mu_w, ls_w, (float*)phm, (float*)phl);
    gcn_edge_kernel<<<NE / 16, 256>>>(ei, (float*)phm, (float*)phl, (float*)pdinv,
                                      (float*)paggm, (float*)paggl);
    out_kernel<<<(NN * 16 + 255) / 256, 256>>>((float*)paggm, (float*)paggl, (float*)phm,
                                               (float*)phl, (float*)pinvdeg, mu_b, ls_b, out);
}